// round 15
// baseline (speedup 1.0000x reference)
#include <cuda_runtime.h>
#include <cuda_bf16.h>
#include <math.h>
#include <stdint.h>

#define Bb 32
#define Tt 1024
#define Dd 256
#define BT (Bb*Tt)
#define MAXE 64
#define NT 8
#define LN_EPS 1e-5f
#define EPS_ADJ 1e-6f
#define CAP 48
#define MARGIN 0.02f

// ---------------- device scratch ----------------
__device__ float          g_xn[BT*Dd];
__device__ __nv_bfloat16  g_xb[BT*Dd];
__device__ __nv_bfloat16  g_simb[(size_t)BT*Tt];
__device__ float          g_s0[BT*Dd];
__device__ float          g_s1[BT*Dd];
__device__ float          g_mf[BT];
__device__ unsigned       g_bits[BT*(Tt/32)];
__device__ float          g_rinv[BT];
__device__ int            g_ecols[BT*MAXE];
__device__ float          g_evals[BT*MAXE];
__device__ int            g_ecnt[BT];
__device__ float          g_v2a[BT];
__device__ int            g_cand[BT*CAP];
__device__ int            g_ccnt[BT];

__device__ __forceinline__ uint32_t smem_to_u32(const void* p) {
    uint32_t a;
    asm("{ .reg .u64 t; cvta.to.shared.u64 t, %1; cvt.u32.u64 %0, t; }" : "=r"(a) : "l"(p));
    return a;
}
__device__ __forceinline__ void ldsm4(uint32_t& r0, uint32_t& r1, uint32_t& r2, uint32_t& r3, uint32_t addr) {
    asm volatile("ldmatrix.sync.aligned.m8n8.x4.shared.b16 {%0,%1,%2,%3}, [%4];"
                 : "=r"(r0), "=r"(r1), "=r"(r2), "=r"(r3) : "r"(addr));
}
__device__ __forceinline__ void mma_bf16(float* c, uint32_t a0, uint32_t a1, uint32_t a2, uint32_t a3,
                                         uint32_t b0, uint32_t b1) {
    asm volatile("mma.sync.aligned.m16n8k16.row.col.f32.bf16.bf16.f32 "
                 "{%0,%1,%2,%3},{%4,%5,%6,%7},{%8,%9},{%0,%1,%2,%3};"
                 : "+f"(c[0]), "+f"(c[1]), "+f"(c[2]), "+f"(c[3])
                 : "r"(a0), "r"(a1), "r"(a2), "r"(a3), "r"(b0), "r"(b1));
}
__device__ __forceinline__ uint32_t bfpack(float x, float y) {
    __nv_bfloat162 t = __floats2bfloat162_rn(x, y);
    return *(uint32_t*)&t;
}

// ---------------- normalize + mask + bf16 copy ----------------
__global__ void k_normalize(const float* __restrict__ x, const int* __restrict__ mask) {
    int row = blockIdx.x;
    int d = threadIdx.x;
    float v = x[row*Dd + d];
    __shared__ float red[8];
    float ss = v*v;
    #pragma unroll
    for (int o = 16; o; o >>= 1) ss += __shfl_xor_sync(~0u, ss, o);
    if ((threadIdx.x & 31) == 0) red[threadIdx.x >> 5] = ss;
    __syncthreads();
    if (threadIdx.x < 8) {
        float t = red[threadIdx.x];
        #pragma unroll
        for (int o = 4; o; o >>= 1) t += __shfl_xor_sync(0xff, t, o);
        if (threadIdx.x == 0) red[0] = t;
    }
    __syncthreads();
    float rn = 1.f / fmaxf(sqrtf(red[0]), 1e-12f);
    float xv = v * rn;
    g_xn[row*Dd + d] = xv;
    g_xb[row*Dd + d] = __float2bfloat16(xv);
    if (d == 0) g_mf[row] = (float)mask[row];
}

// ============ bf16 HMMA sim: 64-col B chunks, 2 CTAs/SM, reg-prefetch pipeline ============
#define PK 264
#define SMA_BYTES (128*PK*2)
#define SMB_BYTES (64*PK*2)
#define SM_B_OFF  SMA_BYTES
#define SM_MASK_OFF (SMA_BYTES + SMB_BYTES)
#define SM_TOTAL (SMA_BYTES + SMB_BYTES + 4096)

__device__ __forceinline__ void load_rows(__nv_bfloat16* dst, const __nv_bfloat16* src,
                                          int tid, int iters) {
    #pragma unroll
    for (int it = 0; it < 16; it++) {
        if (it >= iters) break;
        int unit = tid + it*256;
        int row = unit >> 5;
        int c8  = (unit & 31) * 8;
        uint4 v = *(const uint4*)(src + row*256 + c8);
        *(uint4*)(dst + row*PK + c8) = v;
    }
}

__global__ __launch_bounds__(256, 2) void k_simtc() {
    extern __shared__ char sm[];
    __nv_bfloat16* As = (__nv_bfloat16*)sm;
    __nv_bfloat16* Bs = (__nv_bfloat16*)(sm + SM_B_OFF);
    float* smask = (float*)(sm + SM_MASK_OFF);
    uint32_t smbA = smem_to_u32(As);
    uint32_t smbB = smem_to_u32(Bs);

    int b  = blockIdx.y;
    int rb = b * Tt;
    int i0 = blockIdx.x * 128;
    int tid = threadIdx.x;
    int w = tid >> 5;
    int l = tid & 31;
    int quad = l & 3, qrow = l >> 2;

    // per-thread B loader geometry (8 uint4 per chunk)
    int ldrow = tid >> 5;          // 0..7 within 8-row step
    int ldc8  = (tid & 31) * 8;

    #pragma unroll
    for (int u = 0; u < 4; u++) smask[tid + u*256] = g_mf[rb + tid + u*256];

    load_rows(As, g_xb + (size_t)(rb + i0)*Dd, tid, 16);

    int irow0 = i0 + w*16 + qrow;
    int irow1 = irow0 + 8;
    float mi0 = g_mf[rb + irow0];
    float mi1 = g_mf[rb + irow1];

    uint32_t aBase = smbA + (uint32_t)(((w*16 + (l & 15))*PK + ((l >> 4) << 3)) * 2);
    uint32_t bBase = smbB + (uint32_t)(((((l >> 4) << 3) + (l & 7))*PK + (((l >> 3) & 1) << 3)) * 2);

    float v1a = -1e30f, v2a = -1e30f, v1b = -1e30f, v2b = -1e30f;

    // prefetch chunk 0 into registers
    uint4 pre[8];
    {
        const __nv_bfloat16* src = g_xb + (size_t)rb*Dd;
        #pragma unroll
        for (int it = 0; it < 8; it++)
            pre[it] = *(const uint4*)(src + (it*8 + ldrow)*256 + ldc8);
    }

    for (int jc = 0; jc < 16; jc++) {
        __syncthreads();          // previous MMA done reading Bs
        #pragma unroll
        for (int it = 0; it < 8; it++)
            *(uint4*)(Bs + (it*8 + ldrow)*PK + ldc8) = pre[it];
        __syncthreads();          // Bs ready

        // prefetch next chunk (LDG latency hidden by MMA below)
        if (jc + 1 < 16) {
            const __nv_bfloat16* src = g_xb + (size_t)(rb + (jc+1)*64)*Dd;
            #pragma unroll
            for (int it = 0; it < 8; it++)
                pre[it] = *(const uint4*)(src + (it*8 + ldrow)*256 + ldc8);
        }

        float acc[8][4];
        #pragma unroll
        for (int n = 0; n < 8; n++)
            #pragma unroll
            for (int q = 0; q < 4; q++) acc[n][q] = 0.f;

        #pragma unroll
        for (int kk = 0; kk < 16; kk++) {
            uint32_t a0, a1, a2, a3;
            ldsm4(a0, a1, a2, a3, aBase + kk*32);
            #pragma unroll
            for (int p = 0; p < 4; p++) {
                uint32_t b0, b1, b2, b3;
                ldsm4(b0, b1, b2, b3, bBase + p*(16*PK*2) + kk*32);
                mma_bf16(acc[2*p],   a0, a1, a2, a3, b0, b1);
                mma_bf16(acc[2*p+1], a0, a1, a2, a3, b2, b3);
            }
        }

        #pragma unroll
        for (int n = 0; n < 8; n++) {
            int col = jc*64 + n*8 + quad*2;
            float s0 = acc[n][0] * mi0 * smask[col];
            float s1 = acc[n][1] * mi0 * smask[col+1];
            float s2 = acc[n][2] * mi1 * smask[col];
            float s3 = acc[n][3] * mi1 * smask[col+1];
            __nv_bfloat162 h0 = __float22bfloat162_rn(make_float2(s0, s1));
            __nv_bfloat162 h1 = __float22bfloat162_rn(make_float2(s2, s3));
            *(__nv_bfloat162*)&g_simb[(size_t)(rb + irow0)*Tt + col] = h0;
            *(__nv_bfloat162*)&g_simb[(size_t)(rb + irow1)*Tt + col] = h1;
            if (col   != irow0) { if (s0 > v1a) { v2a = v1a; v1a = s0; } else if (s0 > v2a) v2a = s0; }
            if (col+1 != irow0) { if (s1 > v1a) { v2a = v1a; v1a = s1; } else if (s1 > v2a) v2a = s1; }
            if (col   != irow1) { if (s2 > v1b) { v2b = v1b; v1b = s2; } else if (s2 > v2b) v2b = s2; }
            if (col+1 != irow1) { if (s3 > v1b) { v2b = v1b; v1b = s3; } else if (s3 > v2b) v2b = s3; }
        }
    }
    #pragma unroll
    for (int off = 1; off < 4; off <<= 1) {
        float o1 = __shfl_xor_sync(~0u, v1a, off);
        float o2 = __shfl_xor_sync(~0u, v2a, off);
        if (o1 > v1a) { v2a = fmaxf(v1a, o2); v1a = o1; } else v2a = fmaxf(v2a, o1);
        o1 = __shfl_xor_sync(~0u, v1b, off);
        o2 = __shfl_xor_sync(~0u, v2b, off);
        if (o1 > v1b) { v2b = fmaxf(v1b, o2); v1b = o1; } else v2b = fmaxf(v2b, o1);
    }
    if (quad == 0) {
        g_v2a[rb + irow0] = v2a;
        g_v2a[rb + irow1] = v2b;
    }
}

// ---------------- candidate collection (warp per row, order preserved) ----------------
__global__ __launch_bounds__(256) void k_cand() {
    int warp = (blockIdx.x*256 + threadIdx.x) >> 5;
    int lane = threadIdx.x & 31;
    if (warp >= BT) return;
    int row = warp;
    int i = row & (Tt-1);
    float thr = g_v2a[row] - MARGIN;

    uint4 d[4];
    const uint4* p = (const uint4*)(g_simb + (size_t)row*Tt) + lane*4;
    #pragma unroll
    for (int t = 0; t < 4; t++) d[t] = p[t];

    int cnt = 0;
    #pragma unroll
    for (int t = 0; t < 4; t++) {
        uint32_t parts[4] = {d[t].x, d[t].y, d[t].z, d[t].w};
        #pragma unroll
        for (int h = 0; h < 4; h++) {
            float2 f = __bfloat1622float2(*(__nv_bfloat162*)&parts[h]);
            int j0 = lane*32 + t*8 + h*2;
            if (f.x >= thr && j0   != i) cnt++;
            if (f.y >= thr && j0+1 != i) cnt++;
        }
    }
    int incl = cnt;
    #pragma unroll
    for (int off = 1; off < 32; off <<= 1) {
        int n = __shfl_up_sync(~0u, incl, off);
        if (lane >= off) incl += n;
    }
    int base = incl - cnt;
    int total = __shfl_sync(~0u, incl, 31);

    int k = 0;
    #pragma unroll
    for (int t = 0; t < 4; t++) {
        uint32_t parts[4] = {d[t].x, d[t].y, d[t].z, d[t].w};
        #pragma unroll
        for (int h = 0; h < 4; h++) {
            float2 f = __bfloat1622float2(*(__nv_bfloat162*)&parts[h]);
            int j0 = lane*32 + t*8 + h*2;
            if (f.x >= thr && j0 != i) {
                int pos = base + k;
                if (pos < CAP) g_cand[(size_t)row*CAP + pos] = j0;
                k++;
            }
            if (f.y >= thr && j0+1 != i) {
                int pos = base + k;
                if (pos < CAP) g_cand[(size_t)row*CAP + pos] = j0+1;
                k++;
            }
        }
    }
    if (lane == 31) g_ccnt[row] = min(total, CAP);
}

// ---------------- exact fp32 rescore -> top-2, with fused bit-setting ----------------
__device__ __forceinline__ bool tgt(float v, int j, float v2, int j2) {
    return (v > v2) || (v == v2 && j < j2);
}

__global__ __launch_bounds__(256) void k_rescore() {
    int warp = (blockIdx.x*256 + threadIdx.x) >> 5;
    int lane = threadIdx.x & 31;
    if (warp >= BT) return;
    int row = warp;
    int b = row / Tt;
    float a[8];
    #pragma unroll
    for (int u = 0; u < 8; u++) a[u] = g_xn[row*Dd + lane + 32*u];
    float mi = g_mf[row];
    int cnt = g_ccnt[row];
    float v1 = -1e30f, v2 = -1e30f; int j1 = 0, j2 = 0;
    for (int e = 0; e < cnt; e++) {
        int j = g_cand[(size_t)row*CAP + e];
        int jr = b*Tt + j;
        float dot = 0.f;
        #pragma unroll
        for (int u = 0; u < 8; u++) dot = fmaf(a[u], g_xn[jr*Dd + lane + 32*u], dot);
        #pragma unroll
        for (int o = 16; o; o >>= 1) dot += __shfl_xor_sync(~0u, dot, o);
        float s = dot * mi * g_mf[jr];
        if (tgt(s, j, v1, j1)) { v2 = v1; j2 = j1; v1 = s; j1 = j; }
        else if (tgt(s, j, v2, j2)) { v2 = s; j2 = j; }
    }
    if (lane == 0) {
        int i = row & (Tt-1);
        unsigned* wb = &g_bits[row*(Tt/32)];
        atomicOr(&wb[i >> 5], 1u << (i & 31));
        if (i > 0)      atomicOr(&wb[(i-1) >> 5], 1u << ((i-1) & 31));
        if (i < Tt-1)   atomicOr(&wb[(i+1) >> 5], 1u << ((i+1) & 31));
        int tk0 = j1, tk1 = j2;
        float mj0 = g_mf[b*Tt + tk0];
        float mj1 = g_mf[b*Tt + tk1];
        if (mi*mj0 != 0.f) {
            atomicOr(&wb[tk0 >> 5], 1u << (tk0 & 31));
            atomicOr(&g_bits[(b*Tt + tk0)*(Tt/32) + (i >> 5)], 1u << (i & 31));
        }
        if (mi*mj1 != 0.f) {
            atomicOr(&wb[tk1 >> 5], 1u << (tk1 & 31));
            atomicOr(&g_bits[(b*Tt + tk1)*(Tt/32) + (i >> 5)], 1u << (i & 31));
        }
    }
}

// ---------------- adjacency bitmap clear ----------------
__global__ void k_clear() {
    int i = blockIdx.x*256 + threadIdx.x;
    if (i < BT*(Tt/32)) g_bits[i] = 0u;
}

// ---------------- edge extraction (warp per row) ----------------
__global__ __launch_bounds__(256) void k_edges() {
    int warp = (blockIdx.x*256 + threadIdx.x) >> 5;
    int lane = threadIdx.x & 31;
    if (warp >= BT) return;
    int row = warp;
    int b = row / Tt, i = row % Tt;
    float a[8];
    #pragma unroll
    for (int u = 0; u < 8; u++) a[u] = g_xn[row*Dd + lane + 32*u];
    float mi = g_mf[row];
    float rowsum = 0.f;
    int cnt = 0;
    for (int w = 0; w < Tt/32; w++) {
        unsigned bitsw = g_bits[row*(Tt/32) + w];
        while (bitsw) {
            int bit = __ffs(bitsw) - 1;
            bitsw &= bitsw - 1;
            int j = w*32 + bit;
            int jr = b*Tt + j;
            float dot = 0.f;
            #pragma unroll
            for (int u = 0; u < 8; u++) dot = fmaf(a[u], g_xn[jr*Dd + lane + 32*u], dot);
            #pragma unroll
            for (int o = 16; o; o >>= 1) dot += __shfl_xor_sync(~0u, dot, o);
            float val = dot * mi * g_mf[jr];
            if (j == i) val += 1.0f;
            rowsum += val;
            if (lane == 0 && cnt < MAXE) {
                g_ecols[row*MAXE + cnt] = j;
                g_evals[row*MAXE + cnt] = val;
            }
            cnt++;
        }
    }
    if (lane == 0) {
        g_ecnt[row] = min(cnt, MAXE);
        g_rinv[row] = rsqrtf(rowsum + EPS_ADJ);
    }
}

// ---------------- sparse adj @ h ----------------
__global__ __launch_bounds__(256) void k_spmm(const float* __restrict__ hin,
                                              float* __restrict__ hout) {
    int row = blockIdx.x;
    int d = threadIdx.x;
    int b = row / Tt;
    int cnt = g_ecnt[row];
    float ri = g_rinv[row], mi = g_mf[row];
    float acc = 0.f;
    for (int e = 0; e < cnt; e++) {
        int j = g_ecols[row*MAXE + e];
        int jr = b*Tt + j;
        float w = g_evals[row*MAXE + e] * ri * g_rinv[jr] * mi * g_mf[jr];
        acc = fmaf(w, hin[jr*Dd + d], acc);
    }
    hout[row*Dd + d] = acc;
}

// ======== bf16 3-term split HMMA GEMM, ldmatrix fragment loads ========
#define SP 20
#define SAH 0
#define SAL (128*SP)
#define SBH (2*128*SP)
#define SBL (3*128*SP)

__global__ __launch_bounds__(256, 2) void k_gemm_bf16s(const float* __restrict__ A,
                                                       const float* __restrict__ W,
                                                       const float* __restrict__ bias,
                                                       float* __restrict__ out) {
    __shared__ uint32_t gsm[4*128*SP];
    uint32_t gsb = smem_to_u32(gsm);
    int r0 = blockIdx.x * 128;
    int o0 = blockIdx.y * 128;
    int tid = threadIdx.x;
    int w = tid >> 5;
    int lane = tid & 31;
    int lr = lane >> 2;
    int lc = lane & 3;

    float acc[16][4];
    #pragma unroll
    for (int n = 0; n < 16; n++)
        #pragma unroll
        for (int q = 0; q < 4; q++) acc[n][q] = 0.f;

    int m0 = w * 16;

    uint32_t aBaseH = gsb + SAH*4 + (uint32_t)((m0 + (lane & 15))*80 + ((lane >> 4) << 4));
    uint32_t aBaseL = aBaseH + (SAL - SAH)*4;
    uint32_t bBaseH = gsb + SBH*4 + (uint32_t)(((((lane >> 4) << 3) + (lane & 7))*80) + (((lane >> 3) & 1) << 4));
    uint32_t bBaseL = bBaseH + (SBL - SBH)*4;

    for (int kc = 0; kc < 8; kc++) {
        __syncthreads();
        #pragma unroll
        for (int t = 0; t < 4; t++) {
            int unit = tid + t*256;
            int row = unit >> 3;
            int k4  = (unit & 7) * 4;
            float4 av = *(const float4*)&A[(size_t)(r0+row)*Dd + kc*32 + k4];
            float4 wv = *(const float4*)&W[(size_t)(o0+row)*Dd + kc*32 + k4];
            float ahx = __bfloat162float(__float2bfloat16(av.x));
            float ahy = __bfloat162float(__float2bfloat16(av.y));
            float ahz = __bfloat162float(__float2bfloat16(av.z));
            float ahw = __bfloat162float(__float2bfloat16(av.w));
            float whx = __bfloat162float(__float2bfloat16(wv.x));
            float why = __bfloat162float(__float2bfloat16(wv.y));
            float whz = __bfloat162float(__float2bfloat16(wv.z));
            float whw = __bfloat162float(__float2bfloat16(wv.w));
            int wbase = row*SP + (k4 >> 1);
            gsm[SAH + wbase]     = bfpack(ahx, ahy);
            gsm[SAH + wbase + 1] = bfpack(ahz, ahw);
            gsm[SAL + wbase]     = bfpack(av.x - ahx, av.y - ahy);
            gsm[SAL + wbase + 1] = bfpack(av.z - ahz, av.w - ahw);
            gsm[SBH + wbase]     = bfpack(whx, why);
            gsm[SBH + wbase + 1] = bfpack(whz, whw);
            gsm[SBL + wbase]     = bfpack(wv.x - whx, wv.y - why);
            gsm[SBL + wbase + 1] = bfpack(wv.z - whz, wv.w - whw);
        }
        __syncthreads();

        #pragma unroll
        for (int kk = 0; kk < 2; kk++) {
            uint32_t koff = kk * 32;
            uint32_t ah0, ah1, ah2, ah3, al0, al1, al2, al3;
            ldsm4(ah0, ah1, ah2, ah3, aBaseH + koff);
            ldsm4(al0, al1, al2, al3, aBaseL + koff);
            #pragma unroll
            for (int pg = 0; pg < 8; pg++) {
                uint32_t bh0, bh1, bh2, bh3, bl0, bl1, bl2, bl3;
                ldsm4(bh0, bh1, bh2, bh3, bBaseH + pg*(16*80) + koff);
                ldsm4(bl0, bl1, bl2, bl3, bBaseL + pg*(16*80) + koff);
                mma_bf16(acc[2*pg],   ah0, ah1, ah2, ah3, bh0, bh1);
                mma_bf16(acc[2*pg],   ah0, ah1, ah2, ah3, bl0, bl1);
                mma_bf16(acc[2*pg],   al0, al1, al2, al3, bh0, bh1);
                mma_bf16(acc[2*pg+1], ah0, ah1, ah2, ah3, bh2, bh3);
                mma_bf16(acc[2*pg+1], ah0, ah1, ah2, ah3, bl2, bl3);
                mma_bf16(acc[2*pg+1], al0, al1, al2, al3, bh2, bh3);
            }
        }
    }

    #pragma unroll
    for (int p = 0; p < 16; p++) {
        int oc = o0 + p*8 + lc*2;
        float b0 = bias[oc], b1 = bias[oc+1];
        int gr0 = r0 + m0 + lr;
        float v0 = acc[p][0] + b0;
        float v1 = acc[p][1] + b1;
        float v2 = acc[p][2] + b0;
        float v3 = acc[p][3] + b1;
        v0 = (v0 > 0.f) ? v0 : expm1f(v0);
        v1 = (v1 > 0.f) ? v1 : expm1f(v1);
        v2 = (v2 > 0.f) ? v2 : expm1f(v2);
        v3 = (v3 > 0.f) ? v3 : expm1f(v3);
        *(float2*)&out[(size_t)gr0*Dd + oc]     = make_float2(v0, v1);
        *(float2*)&out[(size_t)(gr0+8)*Dd + oc] = make_float2(v2, v3);
    }
}

// ---------------- LayerNorm over D ----------------
__global__ void k_ln(const float* __restrict__ in, const float* __restrict__ g,
                     const float* __restrict__ be, float* __restrict__ out) {
    int row = blockIdx.x;
    int d = threadIdx.x;
    float v = in[row*Dd + d];
    __shared__ float red[8];

    float s = v;
    #pragma unroll
    for (int o = 16; o; o >>= 1) s += __shfl_xor_sync(~0u, s, o);
    if ((threadIdx.x & 31) == 0) red[threadIdx.x >> 5] = s;
    __syncthreads();
    if (threadIdx.x < 8) {
        float t = red[threadIdx.x];
        #pragma unroll
        for (int o = 4; o; o >>= 1) t += __shfl_xor_sync(0xff, t, o);
        if (threadIdx.x == 0) red[0] = t;
    }
    __syncthreads();
    float mu = red[0] * (1.f/Dd);
    __syncthreads();

    float dv = v - mu;
    float s2 = dv*dv;
    #pragma unroll
    for (int o = 16; o; o >>= 1) s2 += __shfl_xor_sync(~0u, s2, o);
    if ((threadIdx.x & 31) == 0) red[threadIdx.x >> 5] = s2;
    __syncthreads();
    if (threadIdx.x < 8) {
        float t = red[threadIdx.x];
        #pragma unroll
        for (int o = 4; o; o >>= 1) t += __shfl_xor_sync(0xff, t, o);
        if (threadIdx.x == 0) red[0] = t;
    }
    __syncthreads();
    float var = red[0] * (1.f/Dd);
    out[row*Dd + d] = dv * rsqrtf(var + LN_EPS) * g[d] + be[d];
}

// ---------------- launch ----------------
extern "C" void kernel_launch(void* const* d_in, const int* in_sizes, int n_in,
                              void* d_out, int out_size) {
    const float* x    = (const float*)d_in[0];
    const int*   mask = (const int*)  d_in[1];
    const float* W0 = (const float*)d_in[2];
    const float* b0 = (const float*)d_in[3];
    const float* g0 = (const float*)d_in[4];
    const float* be0= (const float*)d_in[5];
    const float* W1 = (const float*)d_in[6];
    const float* b1 = (const float*)d_in[7];
    const float* g1 = (const float*)d_in[8];
    const float* be1= (const float*)d_in[9];
    float* out = (float*)d_out;

    float *s0, *s1;
    cudaGetSymbolAddress((void**)&s0, g_s0);
    cudaGetSymbolAddress((void**)&s1, g_s1);

    cudaFuncSetAttribute(k_simtc, cudaFuncAttributeMaxDynamicSharedMemorySize, SM_TOTAL);

    k_normalize<<<BT, 256>>>(x, mask);
    k_clear<<<(BT*(Tt/32) + 255)/256, 256>>>();
    k_simtc<<<dim3(NT, Bb), 256, SM_TOTAL>>>();
    k_cand<<<BT/8, 256>>>();
    k_rescore<<<BT/8, 256>>>();
    k_edges<<<(BT*32)/256, 256>>>();

    // layer 1
    k_spmm<<<BT, 256>>>(x, s0);
    k_gemm_bf16s<<<dim3(BT/128, Dd/128), 256>>>(s0, W0, b0, s1);
    k_ln<<<BT, 256>>>(s1, g0, be0, s0);
    // layer 2
    k_spmm<<<BT, 256>>>(s0, s1);
    k_gemm_bf16s<<<dim3(BT/128, Dd/128), 256>>>(s1, W1, b1, s0);
    k_ln<<<BT, 256>>>(s0, g1, be1, out);
}

// round 16
// speedup vs baseline: 1.0279x; 1.0279x over previous
#include <cuda_runtime.h>
#include <cuda_bf16.h>
#include <math.h>
#include <stdint.h>

#define Bb 32
#define Tt 1024
#define Dd 256
#define BT (Bb*Tt)
#define MAXE 64
#define NT 8
#define LN_EPS 1e-5f
#define EPS_ADJ 1e-6f
#define CAP 48
#define MARGIN 0.02f

// ---------------- device scratch ----------------
__device__ float          g_xn[BT*Dd];
__device__ __nv_bfloat16  g_xb[BT*Dd];
__device__ __nv_bfloat16  g_simb[(size_t)BT*Tt];
__device__ float          g_s0[BT*Dd];
__device__ float          g_s1[BT*Dd];
__device__ float          g_mf[BT];
__device__ unsigned       g_bits[BT*(Tt/32)];
__device__ float          g_rinv[BT];
__device__ int            g_ecols[BT*MAXE];
__device__ float          g_evals[BT*MAXE];
__device__ int            g_ecnt[BT];
__device__ float          g_v2a[BT];

__device__ __forceinline__ uint32_t smem_to_u32(const void* p) {
    uint32_t a;
    asm("{ .reg .u64 t; cvta.to.shared.u64 t, %1; cvt.u32.u64 %0, t; }" : "=r"(a) : "l"(p));
    return a;
}
__device__ __forceinline__ void ldsm4(uint32_t& r0, uint32_t& r1, uint32_t& r2, uint32_t& r3, uint32_t addr) {
    asm volatile("ldmatrix.sync.aligned.m8n8.x4.shared.b16 {%0,%1,%2,%3}, [%4];"
                 : "=r"(r0), "=r"(r1), "=r"(r2), "=r"(r3) : "r"(addr));
}
__device__ __forceinline__ void mma_bf16(float* c, uint32_t a0, uint32_t a1, uint32_t a2, uint32_t a3,
                                         uint32_t b0, uint32_t b1) {
    asm volatile("mma.sync.aligned.m16n8k16.row.col.f32.bf16.bf16.f32 "
                 "{%0,%1,%2,%3},{%4,%5,%6,%7},{%8,%9},{%0,%1,%2,%3};"
                 : "+f"(c[0]), "+f"(c[1]), "+f"(c[2]), "+f"(c[3])
                 : "r"(a0), "r"(a1), "r"(a2), "r"(a3), "r"(b0), "r"(b1));
}
__device__ __forceinline__ uint32_t bfpack(float x, float y) {
    __nv_bfloat162 t = __floats2bfloat162_rn(x, y);
    return *(uint32_t*)&t;
}

// ---------------- normalize + mask + bf16 copy + bitmap clear ----------------
__global__ void k_normalize(const float* __restrict__ x, const int* __restrict__ mask) {
    int row = blockIdx.x;
    int d = threadIdx.x;
    float v = x[row*Dd + d];
    __shared__ float red[8];
    float ss = v*v;
    #pragma unroll
    for (int o = 16; o; o >>= 1) ss += __shfl_xor_sync(~0u, ss, o);
    if ((threadIdx.x & 31) == 0) red[threadIdx.x >> 5] = ss;
    __syncthreads();
    if (threadIdx.x < 8) {
        float t = red[threadIdx.x];
        #pragma unroll
        for (int o = 4; o; o >>= 1) t += __shfl_xor_sync(0xff, t, o);
        if (threadIdx.x == 0) red[0] = t;
    }
    __syncthreads();
    float rn = 1.f / fmaxf(sqrtf(red[0]), 1e-12f);
    float xv = v * rn;
    g_xn[row*Dd + d] = xv;
    g_xb[row*Dd + d] = __float2bfloat16(xv);
    if (d == 0) g_mf[row] = (float)mask[row];
    if (d < Tt/32) g_bits[row*(Tt/32) + d] = 0u;   // fused bitmap clear
}

// ============ bf16 HMMA sim: 64-col B chunks, 2 CTAs/SM ============
#define PK 264
#define SMA_BYTES (128*PK*2)
#define SMB_BYTES (64*PK*2)
#define SM_B_OFF  SMA_BYTES
#define SM_MASK_OFF (SMA_BYTES + SMB_BYTES)
#define SM_TOTAL (SMA_BYTES + SMB_BYTES + 4096)

__device__ __forceinline__ void load_rows(__nv_bfloat16* dst, const __nv_bfloat16* src,
                                          int tid, int iters) {
    #pragma unroll
    for (int it = 0; it < 16; it++) {
        if (it >= iters) break;
        int unit = tid + it*256;
        int row = unit >> 5;
        int c8  = (unit & 31) * 8;
        uint4 v = *(const uint4*)(src + row*256 + c8);
        *(uint4*)(dst + row*PK + c8) = v;
    }
}

__global__ __launch_bounds__(256, 2) void k_simtc() {
    extern __shared__ char sm[];
    __nv_bfloat16* As = (__nv_bfloat16*)sm;
    __nv_bfloat16* Bs = (__nv_bfloat16*)(sm + SM_B_OFF);
    float* smask = (float*)(sm + SM_MASK_OFF);
    uint32_t smbA = smem_to_u32(As);
    uint32_t smbB = smem_to_u32(Bs);

    int b  = blockIdx.y;
    int rb = b * Tt;
    int i0 = blockIdx.x * 128;
    int tid = threadIdx.x;
    int w = tid >> 5;
    int l = tid & 31;
    int quad = l & 3, qrow = l >> 2;

    #pragma unroll
    for (int u = 0; u < 4; u++) smask[tid + u*256] = g_mf[rb + tid + u*256];

    load_rows(As, g_xb + (size_t)(rb + i0)*Dd, tid, 16);

    int irow0 = i0 + w*16 + qrow;
    int irow1 = irow0 + 8;
    float mi0 = g_mf[rb + irow0];
    float mi1 = g_mf[rb + irow1];

    uint32_t aBase = smbA + (uint32_t)(((w*16 + (l & 15))*PK + ((l >> 4) << 3)) * 2);
    uint32_t bBase = smbB + (uint32_t)(((((l >> 4) << 3) + (l & 7))*PK + (((l >> 3) & 1) << 3)) * 2);

    float v1a = -1e30f, v2a = -1e30f, v1b = -1e30f, v2b = -1e30f;

    for (int jc = 0; jc < 16; jc++) {
        __syncthreads();
        load_rows(Bs, g_xb + (size_t)(rb + jc*64)*Dd, tid, 8);
        __syncthreads();

        float acc[8][4];
        #pragma unroll
        for (int n = 0; n < 8; n++)
            #pragma unroll
            for (int q = 0; q < 4; q++) acc[n][q] = 0.f;

        #pragma unroll
        for (int kk = 0; kk < 16; kk++) {
            uint32_t a0, a1, a2, a3;
            ldsm4(a0, a1, a2, a3, aBase + kk*32);
            #pragma unroll
            for (int p = 0; p < 4; p++) {
                uint32_t b0, b1, b2, b3;
                ldsm4(b0, b1, b2, b3, bBase + p*(16*PK*2) + kk*32);
                mma_bf16(acc[2*p],   a0, a1, a2, a3, b0, b1);
                mma_bf16(acc[2*p+1], a0, a1, a2, a3, b2, b3);
            }
        }

        #pragma unroll
        for (int n = 0; n < 8; n++) {
            int col = jc*64 + n*8 + quad*2;
            float s0 = acc[n][0] * mi0 * smask[col];
            float s1 = acc[n][1] * mi0 * smask[col+1];
            float s2 = acc[n][2] * mi1 * smask[col];
            float s3 = acc[n][3] * mi1 * smask[col+1];
            __nv_bfloat162 h0 = __float22bfloat162_rn(make_float2(s0, s1));
            __nv_bfloat162 h1 = __float22bfloat162_rn(make_float2(s2, s3));
            *(__nv_bfloat162*)&g_simb[(size_t)(rb + irow0)*Tt + col] = h0;
            *(__nv_bfloat162*)&g_simb[(size_t)(rb + irow1)*Tt + col] = h1;
            if (col   != irow0) { if (s0 > v1a) { v2a = v1a; v1a = s0; } else if (s0 > v2a) v2a = s0; }
            if (col+1 != irow0) { if (s1 > v1a) { v2a = v1a; v1a = s1; } else if (s1 > v2a) v2a = s1; }
            if (col   != irow1) { if (s2 > v1b) { v2b = v1b; v1b = s2; } else if (s2 > v2b) v2b = s2; }
            if (col+1 != irow1) { if (s3 > v1b) { v2b = v1b; v1b = s3; } else if (s3 > v2b) v2b = s3; }
        }
    }
    #pragma unroll
    for (int off = 1; off < 4; off <<= 1) {
        float o1 = __shfl_xor_sync(~0u, v1a, off);
        float o2 = __shfl_xor_sync(~0u, v2a, off);
        if (o1 > v1a) { v2a = fmaxf(v1a, o2); v1a = o1; } else v2a = fmaxf(v2a, o1);
        o1 = __shfl_xor_sync(~0u, v1b, off);
        o2 = __shfl_xor_sync(~0u, v2b, off);
        if (o1 > v1b) { v2b = fmaxf(v1b, o2); v1b = o1; } else v2b = fmaxf(v2b, o1);
    }
    if (quad == 0) {
        g_v2a[rb + irow0] = v2a;
        g_v2a[rb + irow1] = v2b;
    }
}

// ---- fused candidate scan + exact fp32 rescore + bit-setting (warp per row) ----
__device__ __forceinline__ bool tgt(float v, int j, float v2, int j2) {
    return (v > v2) || (v == v2 && j < j2);
}

__global__ __launch_bounds__(256) void k_candrescore() {
    __shared__ int cs[8][CAP];
    int warp = (blockIdx.x*256 + threadIdx.x) >> 5;
    int lw = (threadIdx.x >> 5) & 7;
    int lane = threadIdx.x & 31;
    if (warp >= BT) return;
    int row = warp;
    int i = row & (Tt-1);
    int b = row / Tt;
    float thr = g_v2a[row] - MARGIN;

    uint4 d[4];
    const uint4* p = (const uint4*)(g_simb + (size_t)row*Tt) + lane*4;
    #pragma unroll
    for (int t = 0; t < 4; t++) d[t] = p[t];

    int cnt = 0;
    #pragma unroll
    for (int t = 0; t < 4; t++) {
        uint32_t parts[4] = {d[t].x, d[t].y, d[t].z, d[t].w};
        #pragma unroll
        for (int h = 0; h < 4; h++) {
            float2 f = __bfloat1622float2(*(__nv_bfloat162*)&parts[h]);
            int j0 = lane*32 + t*8 + h*2;
            if (f.x >= thr && j0   != i) cnt++;
            if (f.y >= thr && j0+1 != i) cnt++;
        }
    }
    int incl = cnt;
    #pragma unroll
    for (int off = 1; off < 32; off <<= 1) {
        int n = __shfl_up_sync(~0u, incl, off);
        if (lane >= off) incl += n;
    }
    int base = incl - cnt;
    int total = __shfl_sync(~0u, incl, 31);

    int k = 0;
    #pragma unroll
    for (int t = 0; t < 4; t++) {
        uint32_t parts[4] = {d[t].x, d[t].y, d[t].z, d[t].w};
        #pragma unroll
        for (int h = 0; h < 4; h++) {
            float2 f = __bfloat1622float2(*(__nv_bfloat162*)&parts[h]);
            int j0 = lane*32 + t*8 + h*2;
            if (f.x >= thr && j0 != i) {
                int pos = base + k;
                if (pos < CAP) cs[lw][pos] = j0;
                k++;
            }
            if (f.y >= thr && j0+1 != i) {
                int pos = base + k;
                if (pos < CAP) cs[lw][pos] = j0+1;
                k++;
            }
        }
    }
    __syncwarp();
    int ccnt = min(total, CAP);

    float a[8];
    #pragma unroll
    for (int u = 0; u < 8; u++) a[u] = g_xn[row*Dd + lane + 32*u];
    float mi = g_mf[row];
    float v1 = -1e30f, v2 = -1e30f; int j1 = 0, j2 = 0;
    for (int e = 0; e < ccnt; e++) {
        int j = cs[lw][e];
        int jr = b*Tt + j;
        float dot = 0.f;
        #pragma unroll
        for (int u = 0; u < 8; u++) dot = fmaf(a[u], g_xn[jr*Dd + lane + 32*u], dot);
        #pragma unroll
        for (int o = 16; o; o >>= 1) dot += __shfl_xor_sync(~0u, dot, o);
        float s = dot * mi * g_mf[jr];
        if (tgt(s, j, v1, j1)) { v2 = v1; j2 = j1; v1 = s; j1 = j; }
        else if (tgt(s, j, v2, j2)) { v2 = s; j2 = j; }
    }
    if (lane == 0) {
        unsigned* wb = &g_bits[row*(Tt/32)];
        atomicOr(&wb[i >> 5], 1u << (i & 31));
        if (i > 0)      atomicOr(&wb[(i-1) >> 5], 1u << ((i-1) & 31));
        if (i < Tt-1)   atomicOr(&wb[(i+1) >> 5], 1u << ((i+1) & 31));
        float mj0 = g_mf[b*Tt + j1];
        float mj1 = g_mf[b*Tt + j2];
        if (mi*mj0 != 0.f) {
            atomicOr(&wb[j1 >> 5], 1u << (j1 & 31));
            atomicOr(&g_bits[(b*Tt + j1)*(Tt/32) + (i >> 5)], 1u << (i & 31));
        }
        if (mi*mj1 != 0.f) {
            atomicOr(&wb[j2 >> 5], 1u << (j2 & 31));
            atomicOr(&g_bits[(b*Tt + j2)*(Tt/32) + (i >> 5)], 1u << (i & 31));
        }
    }
}

// ---------------- edge extraction (warp per row) ----------------
__global__ __launch_bounds__(256) void k_edges() {
    int warp = (blockIdx.x*256 + threadIdx.x) >> 5;
    int lane = threadIdx.x & 31;
    if (warp >= BT) return;
    int row = warp;
    int b = row / Tt, i = row % Tt;
    float a[8];
    #pragma unroll
    for (int u = 0; u < 8; u++) a[u] = g_xn[row*Dd + lane + 32*u];
    float mi = g_mf[row];
    float rowsum = 0.f;
    int cnt = 0;
    for (int w = 0; w < Tt/32; w++) {
        unsigned bitsw = g_bits[row*(Tt/32) + w];
        while (bitsw) {
            int bit = __ffs(bitsw) - 1;
            bitsw &= bitsw - 1;
            int j = w*32 + bit;
            int jr = b*Tt + j;
            float dot = 0.f;
            #pragma unroll
            for (int u = 0; u < 8; u++) dot = fmaf(a[u], g_xn[jr*Dd + lane + 32*u], dot);
            #pragma unroll
            for (int o = 16; o; o >>= 1) dot += __shfl_xor_sync(~0u, dot, o);
            float val = dot * mi * g_mf[jr];
            if (j == i) val += 1.0f;
            rowsum += val;
            if (lane == 0 && cnt < MAXE) {
                g_ecols[row*MAXE + cnt] = j;
                g_evals[row*MAXE + cnt] = val;
            }
            cnt++;
        }
    }
    if (lane == 0) {
        g_ecnt[row] = min(cnt, MAXE);
        g_rinv[row] = rsqrtf(rowsum + EPS_ADJ);
    }
}

// ---------------- sparse adj @ h ----------------
__global__ __launch_bounds__(256) void k_spmm(const float* __restrict__ hin,
                                              float* __restrict__ hout) {
    int row = blockIdx.x;
    int d = threadIdx.x;
    int b = row / Tt;
    int cnt = g_ecnt[row];
    float ri = g_rinv[row], mi = g_mf[row];
    float acc = 0.f;
    for (int e = 0; e < cnt; e++) {
        int j = g_ecols[row*MAXE + e];
        int jr = b*Tt + j;
        float w = g_evals[row*MAXE + e] * ri * g_rinv[jr] * mi * g_mf[jr];
        acc = fmaf(w, hin[jr*Dd + d], acc);
    }
    hout[row*Dd + d] = acc;
}

// ======== bf16 3-term split HMMA GEMM, ldmatrix fragment loads ========
#define SP 20
#define SAH 0
#define SAL (128*SP)
#define SBH (2*128*SP)
#define SBL (3*128*SP)

__global__ __launch_bounds__(256, 2) void k_gemm_bf16s(const float* __restrict__ A,
                                                       const float* __restrict__ W,
                                                       const float* __restrict__ bias,
                                                       float* __restrict__ out) {
    __shared__ uint32_t gsm[4*128*SP];
    uint32_t gsb = smem_to_u32(gsm);
    int r0 = blockIdx.x * 128;
    int o0 = blockIdx.y * 128;
    int tid = threadIdx.x;
    int w = tid >> 5;
    int lane = tid & 31;
    int lr = lane >> 2;
    int lc = lane & 3;

    float acc[16][4];
    #pragma unroll
    for (int n = 0; n < 16; n++)
        #pragma unroll
        for (int q = 0; q < 4; q++) acc[n][q] = 0.f;

    int m0 = w * 16;

    uint32_t aBaseH = gsb + SAH*4 + (uint32_t)((m0 + (lane & 15))*80 + ((lane >> 4) << 4));
    uint32_t aBaseL = aBaseH + (SAL - SAH)*4;
    uint32_t bBaseH = gsb + SBH*4 + (uint32_t)(((((lane >> 4) << 3) + (lane & 7))*80) + (((lane >> 3) & 1) << 4));
    uint32_t bBaseL = bBaseH + (SBL - SBH)*4;

    for (int kc = 0; kc < 8; kc++) {
        __syncthreads();
        #pragma unroll
        for (int t = 0; t < 4; t++) {
            int unit = tid + t*256;
            int row = unit >> 3;
            int k4  = (unit & 7) * 4;
            float4 av = *(const float4*)&A[(size_t)(r0+row)*Dd + kc*32 + k4];
            float4 wv = *(const float4*)&W[(size_t)(o0+row)*Dd + kc*32 + k4];
            float ahx = __bfloat162float(__float2bfloat16(av.x));
            float ahy = __bfloat162float(__float2bfloat16(av.y));
            float ahz = __bfloat162float(__float2bfloat16(av.z));
            float ahw = __bfloat162float(__float2bfloat16(av.w));
            float whx = __bfloat162float(__float2bfloat16(wv.x));
            float why = __bfloat162float(__float2bfloat16(wv.y));
            float whz = __bfloat162float(__float2bfloat16(wv.z));
            float whw = __bfloat162float(__float2bfloat16(wv.w));
            int wbase = row*SP + (k4 >> 1);
            gsm[SAH + wbase]     = bfpack(ahx, ahy);
            gsm[SAH + wbase + 1] = bfpack(ahz, ahw);
            gsm[SAL + wbase]     = bfpack(av.x - ahx, av.y - ahy);
            gsm[SAL + wbase + 1] = bfpack(av.z - ahz, av.w - ahw);
            gsm[SBH + wbase]     = bfpack(whx, why);
            gsm[SBH + wbase + 1] = bfpack(whz, whw);
            gsm[SBL + wbase]     = bfpack(wv.x - whx, wv.y - why);
            gsm[SBL + wbase + 1] = bfpack(wv.z - whz, wv.w - whw);
        }
        __syncthreads();

        #pragma unroll
        for (int kk = 0; kk < 2; kk++) {
            uint32_t koff = kk * 32;
            uint32_t ah0, ah1, ah2, ah3, al0, al1, al2, al3;
            ldsm4(ah0, ah1, ah2, ah3, aBaseH + koff);
            ldsm4(al0, al1, al2, al3, aBaseL + koff);
            #pragma unroll
            for (int pg = 0; pg < 8; pg++) {
                uint32_t bh0, bh1, bh2, bh3, bl0, bl1, bl2, bl3;
                ldsm4(bh0, bh1, bh2, bh3, bBaseH + pg*(16*80) + koff);
                ldsm4(bl0, bl1, bl2, bl3, bBaseL + pg*(16*80) + koff);
                mma_bf16(acc[2*pg],   ah0, ah1, ah2, ah3, bh0, bh1);
                mma_bf16(acc[2*pg],   ah0, ah1, ah2, ah3, bl0, bl1);
                mma_bf16(acc[2*pg],   al0, al1, al2, al3, bh0, bh1);
                mma_bf16(acc[2*pg+1], ah0, ah1, ah2, ah3, bh2, bh3);
                mma_bf16(acc[2*pg+1], ah0, ah1, ah2, ah3, bl2, bl3);
                mma_bf16(acc[2*pg+1], al0, al1, al2, al3, bh2, bh3);
            }
        }
    }

    #pragma unroll
    for (int p = 0; p < 16; p++) {
        int oc = o0 + p*8 + lc*2;
        float b0 = bias[oc], b1 = bias[oc+1];
        int gr0 = r0 + m0 + lr;
        float v0 = acc[p][0] + b0;
        float v1 = acc[p][1] + b1;
        float v2 = acc[p][2] + b0;
        float v3 = acc[p][3] + b1;
        v0 = (v0 > 0.f) ? v0 : expm1f(v0);
        v1 = (v1 > 0.f) ? v1 : expm1f(v1);
        v2 = (v2 > 0.f) ? v2 : expm1f(v2);
        v3 = (v3 > 0.f) ? v3 : expm1f(v3);
        *(float2*)&out[(size_t)gr0*Dd + oc]     = make_float2(v0, v1);
        *(float2*)&out[(size_t)(gr0+8)*Dd + oc] = make_float2(v2, v3);
    }
}

// ---------------- LayerNorm over D ----------------
__global__ void k_ln(const float* __restrict__ in, const float* __restrict__ g,
                     const float* __restrict__ be, float* __restrict__ out) {
    int row = blockIdx.x;
    int d = threadIdx.x;
    float v = in[row*Dd + d];
    __shared__ float red[8];

    float s = v;
    #pragma unroll
    for (int o = 16; o; o >>= 1) s += __shfl_xor_sync(~0u, s, o);
    if ((threadIdx.x & 31) == 0) red[threadIdx.x >> 5] = s;
    __syncthreads();
    if (threadIdx.x < 8) {
        float t = red[threadIdx.x];
        #pragma unroll
        for (int o = 4; o; o >>= 1) t += __shfl_xor_sync(0xff, t, o);
        if (threadIdx.x == 0) red[0] = t;
    }
    __syncthreads();
    float mu = red[0] * (1.f/Dd);
    __syncthreads();

    float dv = v - mu;
    float s2 = dv*dv;
    #pragma unroll
    for (int o = 16; o; o >>= 1) s2 += __shfl_xor_sync(~0u, s2, o);
    if ((threadIdx.x & 31) == 0) red[threadIdx.x >> 5] = s2;
    __syncthreads();
    if (threadIdx.x < 8) {
        float t = red[threadIdx.x];
        #pragma unroll
        for (int o = 4; o; o >>= 1) t += __shfl_xor_sync(0xff, t, o);
        if (threadIdx.x == 0) red[0] = t;
    }
    __syncthreads();
    float var = red[0] * (1.f/Dd);
    out[row*Dd + d] = dv * rsqrtf(var + LN_EPS) * g[d] + be[d];
}

// ---------------- launch ----------------
extern "C" void kernel_launch(void* const* d_in, const int* in_sizes, int n_in,
                              void* d_out, int out_size) {
    const float* x    = (const float*)d_in[0];
    const int*   mask = (const int*)  d_in[1];
    const float* W0 = (const float*)d_in[2];
    const float* b0 = (const float*)d_in[3];
    const float* g0 = (const float*)d_in[4];
    const float* be0= (const float*)d_in[5];
    const float* W1 = (const float*)d_in[6];
    const float* b1 = (const float*)d_in[7];
    const float* g1 = (const float*)d_in[8];
    const float* be1= (const float*)d_in[9];
    float* out = (float*)d_out;

    float *s0, *s1;
    cudaGetSymbolAddress((void**)&s0, g_s0);
    cudaGetSymbolAddress((void**)&s1, g_s1);

    cudaFuncSetAttribute(k_simtc, cudaFuncAttributeMaxDynamicSharedMemorySize, SM_TOTAL);

    k_normalize<<<BT, 256>>>(x, mask);
    k_simtc<<<dim3(NT, Bb), 256, SM_TOTAL>>>();
    k_candrescore<<<BT/8, 256>>>();
    k_edges<<<(BT*32)/256, 256>>>();

    // layer 1
    k_spmm<<<BT, 256>>>(x, s0);
    k_gemm_bf16s<<<dim3(BT/128, Dd/128), 256>>>(s0, W0, b0, s1);
    k_ln<<<BT, 256>>>(s1, g0, be0, s0);
    // layer 2
    k_spmm<<<BT, 256>>>(s0, s1);
    k_gemm_bf16s<<<dim3(BT/128, Dd/128), 256>>>(s1, W1, b1, s0);
    k_ln<<<BT, 256>>>(s0, g1, be1, out);
}